// round 2
// baseline (speedup 1.0000x reference)
#include <cuda_runtime.h>

#define BN 16
#define LEN 1024
#define DM 6
#define EDx 48
#define NS 32
#define NT 16        // time tiles per sequence
#define TT 64        // timesteps per tile
#define HALO 15
#define EPSV 1e-5f

// ---------------- scratch (device globals; no allocations) ----------------
__device__ float2 g_P [2][BN*EDx*LEN];       // {delta, xs} per (b,e,t)   6.3MB x2
__device__ float  g_BC[2][BN*LEN*2*NS];      // interleaved {B_n, C_n}    4MB x2
__device__ float  g_z [2][BN*LEN*EDx];       // gate z                    3MB x2
__device__ float  g_y1[BN*EDx*LEN];          // layer-1 scan output (incl D*xs)
__device__ float  g_fi[BN*EDx];              // features into head

__device__ __forceinline__ float ex2f(float x){ float r; asm("ex2.approx.ftz.f32 %0, %1;":"=f"(r):"f"(x)); return r; }
__device__ __forceinline__ float siluf(float x){ return x/(1.f+__expf(-x)); }
__device__ __forceinline__ float softplusf(float x){ return (x>20.f)? x : log1pf(__expf(x)); }

struct SmemPre {
  float u [(TT+HALO)*DM];     // rmsnorm'ed input
  float sp[(TT+HALO)*EDx];    // pre-conv xs
  float xc[TT*EDx];           // post-conv silu(xs)
  float cw[EDx*16];           // conv weights
  float wx[EDx*65];           // x_proj weights
  float dlt[TT];              // raw dt
};

// Shared tail: xs_pre -> conv -> silu -> x_proj -> softplus(delta); emits P/BC/z.
template<int LAYER>
__device__ void pre_tail(SmemPre& s, int b, int t0,
    const float* __restrict__ Win, const float* __restrict__ convw,
    const float* __restrict__ convb, const float* __restrict__ Wx,
    const float* __restrict__ dtw, const float* __restrict__ dtb)
{
  const int tid = threadIdx.x;
  for (int i=tid;i<EDx*16;i+=128) s.cw[i]=convw[i];
  for (int i=tid;i<EDx*65;i+=128) s.wx[i]=Wx[i];
  __syncthreads();
  // xs_pre = u @ Win[:, :48]  (halo positions included)
  for (int idx=tid; idx<(TT+HALO)*EDx; idx+=128){
    int i=idx/EDx, c=idx-i*EDx;
    const float* u=&s.u[i*DM];
    float a=0.f;
    #pragma unroll
    for(int d=0;d<DM;d++) a = fmaf(u[d], __ldg(&Win[d*96+c]), a);
    s.sp[idx]=a;
  }
  // z = u @ Win[:, 48:]  (tile positions only)
  for (int idx=tid; idx<TT*EDx; idx+=128){
    int j=idx/EDx, c=idx-j*EDx;
    const float* u=&s.u[(j+HALO)*DM];
    float a=0.f;
    #pragma unroll
    for(int d=0;d<DM;d++) a = fmaf(u[d], __ldg(&Win[d*96+48+c]), a);
    g_z[LAYER][(b*LEN + t0 + j)*EDx + c] = a;
  }
  __syncthreads();
  // causal depthwise conv (16 taps) + bias + silu
  for (int idx=tid; idx<TT*EDx; idx+=128){
    int j=idx/EDx, c=idx-j*EDx;
    float a=convb[c];
    #pragma unroll
    for(int k=0;k<16;k++) a = fmaf(s.cw[c*16+k], s.sp[(j+k)*EDx+c], a);
    s.xc[idx]=siluf(a);
  }
  __syncthreads();
  // x_proj: 48 -> 65 (dt | B | C)
  for (int idx=tid; idx<TT*65; idx+=128){
    int j=idx/65, m=idx-j*65;
    const float* xr=&s.xc[j*EDx];
    float a=0.f;
    #pragma unroll 12
    for(int c=0;c<EDx;c++) a = fmaf(xr[c], s.wx[c*65+m], a);
    int t=t0+j;
    if(m==0)       s.dlt[j]=a;
    else if(m<33)  g_BC[LAYER][(b*LEN+t)*(2*NS) + (m-1 )*2    ] = a;
    else           g_BC[LAYER][(b*LEN+t)*(2*NS) + (m-33)*2 + 1] = a;
  }
  __syncthreads();
  // delta = softplus(dlt*dt_w + dt_b); pack {delta, xs} per stream (B,ED,L)
  for (int idx=tid; idx<EDx*TT; idx+=128){
    int e=idx/TT, j=idx-e*TT;
    float delta = softplusf(fmaf(s.dlt[j], dtw[e], dtb[e]));
    g_P[LAYER][(b*EDx+e)*LEN + t0 + j] = make_float2(delta, s.xc[j*EDx+e]);
  }
}

__global__ void __launch_bounds__(128) k_pre1(const float* __restrict__ x,
   const float* __restrict__ ip, const float* __restrict__ cw, const float* __restrict__ cb,
   const float* __restrict__ xp, const float* __restrict__ dtw, const float* __restrict__ dtb,
   const float* __restrict__ nw)
{
  __shared__ SmemPre s;
  int b = blockIdx.x >> 4, t0 = (blockIdx.x & 15) * TT;
  int tid = threadIdx.x;
  for (int i=tid;i<TT+HALO;i+=128){
    int t=t0-HALO+i;
    if (t>=0){
      float v[DM]; float ss=0.f;
      #pragma unroll
      for(int d=0;d<DM;d++){ v[d]=x[(b*LEN+t)*DM+d]; ss=fmaf(v[d],v[d],ss); }
      float r = rsqrtf(ss*(1.f/DM)+EPSV);
      #pragma unroll
      for(int d=0;d<DM;d++) s.u[i*DM+d]=v[d]*r*nw[d];
    } else {
      #pragma unroll
      for(int d=0;d<DM;d++) s.u[i*DM+d]=0.f;
    }
  }
  pre_tail<0>(s,b,t0, ip,cw,cb,xp,dtw,dtb);
}

// post-layer1 (gate, out_proj, residual) fused with full layer-2 pre
__global__ void __launch_bounds__(128) k_mid(const float* __restrict__ x,
   const float* __restrict__ ow,
   const float* __restrict__ ip, const float* __restrict__ cw, const float* __restrict__ cb,
   const float* __restrict__ xp, const float* __restrict__ dtw, const float* __restrict__ dtb,
   const float* __restrict__ nw)
{
  __shared__ SmemPre s;
  int b = blockIdx.x >> 4, t0 = (blockIdx.x & 15) * TT;
  int tid = threadIdx.x;
  for (int i=tid;i<TT+HALO;i+=128){
    int t=t0-HALO+i;
    if (t>=0){
      float hd[DM];
      #pragma unroll
      for(int d=0;d<DM;d++) hd[d]=x[(b*LEN+t)*DM+d];   // residual
      for(int e=0;e<EDx;e++){
        float yv = g_y1[(b*EDx+e)*LEN + t];
        float zv = g_z[0][(b*LEN+t)*EDx + e];
        float g  = yv * siluf(zv);
        #pragma unroll
        for(int d=0;d<DM;d++) hd[d] = fmaf(g, __ldg(&ow[e*DM+d]), hd[d]);
      }
      float ss=0.f;
      #pragma unroll
      for(int d=0;d<DM;d++) ss = fmaf(hd[d],hd[d],ss);
      float r = rsqrtf(ss*(1.f/DM)+EPSV);
      #pragma unroll
      for(int d=0;d<DM;d++) s.u[i*DM+d]=hd[d]*r*nw[d];
    } else {
      #pragma unroll
      for(int d=0;d<DM;d++) s.u[i*DM+d]=0.f;
    }
  }
  pre_tail<1>(s,b,t0, ip,cw,cb,xp,dtw,dtb);
}

// Layer-1 selective scan: warp per (b,e), lane = state index n. Emits y per t.
__global__ void __launch_bounds__(128) k_scan1(const float* __restrict__ alog,
                                               const float* __restrict__ Dw)
{
  int b = blockIdx.x / 12;
  int e = (blockIdx.x % 12)*4 + threadIdx.y;
  int lane = threadIdx.x;
  float acoef = -__expf(alog[e*NS+lane]) * 1.4426950408889634f;   // A_n * log2(e)
  float De = Dw[e];
  const float2* __restrict__ P  = &g_P[0][(b*EDx+e)*LEN];
  const float2* __restrict__ BC = (const float2*)&g_BC[0][(size_t)b*LEN*(2*NS)] + lane;
  float* __restrict__ Y = &g_y1[(b*EDx+e)*LEN];
  float h=0.f, ybuf=0.f;
  for (int t0=0;t0<LEN;t0+=32){
    #pragma unroll
    for(int j=0;j<32;j++){
      int t=t0+j;
      float2 p  = P[t];           // {delta, xs} (uniform)
      float2 bc = BC[(size_t)t*NS]; // {B_n, C_n} (per-lane)
      float a = ex2f(p.x*acoef);
      h = fmaf(a, h, (p.x*p.y)*bc.x);
      float sv = h*bc.y;
      #pragma unroll
      for(int o=16;o;o>>=1) sv += __shfl_xor_sync(0xffffffffu, sv, o);
      if (j==lane) ybuf = fmaf(De, p.y, sv);   // + D*xs folded in
    }
    Y[t0+lane]=ybuf;               // coalesced 128B store per warp
  }
}

// Layer-2 scan: only h recurrence; y needed only at t = L-1.
__global__ void __launch_bounds__(128) k_scan2(const float* __restrict__ alog,
                                               const float* __restrict__ Dw)
{
  int b = blockIdx.x / 12;
  int e = (blockIdx.x % 12)*4 + threadIdx.y;
  int lane = threadIdx.x;
  float acoef = -__expf(alog[e*NS+lane]) * 1.4426950408889634f;
  const float2* __restrict__ P  = &g_P[1][(b*EDx+e)*LEN];
  const float2* __restrict__ BC = (const float2*)&g_BC[1][(size_t)b*LEN*(2*NS)] + lane;
  float h=0.f;
  #pragma unroll 8
  for (int t=0;t<LEN-1;t++){
    float2 p  = P[t];
    float2 bc = BC[(size_t)t*NS];
    float a = ex2f(p.x*acoef);
    h = fmaf(a, h, (p.x*p.y)*bc.x);
  }
  // last step + epilogue
  {
    int t = LEN-1;
    float2 p  = P[t];
    float2 bc = BC[(size_t)t*NS];
    float a = ex2f(p.x*acoef);
    h = fmaf(a, h, (p.x*p.y)*bc.x);
    float sv = h*bc.y;
    #pragma unroll
    for(int o=16;o;o>>=1) sv += __shfl_xor_sync(0xffffffffu, sv, o);
    if (lane==0){
      float y  = fmaf(Dw[e], p.y, sv);
      float zv = g_z[1][(b*LEN+t)*EDx + e];
      g_fi[b*EDx+e] = y*siluf(zv);
    }
  }
}

__global__ void __launch_bounds__(256) k_final(
   const float* __restrict__ fcw, const float* __restrict__ fcb,
   const float* __restrict__ clsw, const float* __restrict__ clsb,
   const float* __restrict__ regw, const float* __restrict__ regb,
   float* __restrict__ out)
{
  __shared__ float feat[BN*EDx];
  int tid = threadIdx.x;
  for (int idx=tid; idx<BN*EDx; idx+=256){
    int b=idx/EDx, j=idx-b*EDx;
    float a=fcb[j];
    #pragma unroll 12
    for(int e=0;e<EDx;e++) a = fmaf(g_fi[b*EDx+e], fcw[e*EDx+j], a);
    feat[idx] = fmaxf(a, 0.f);
  }
  __syncthreads();
  if (tid < BN*4){
    int b=tid>>2, k=tid&3;
    float a=clsb[k];
    #pragma unroll 12
    for(int j=0;j<EDx;j++) a = fmaf(feat[b*EDx+j], clsw[j*4+k], a);
    out[b*4+k]=a;
  } else if (tid < BN*4 + BN){
    int b=tid-BN*4;
    float a=regb[0];
    #pragma unroll 12
    for(int j=0;j<EDx;j++) a = fmaf(feat[b*EDx+j], regw[j], a);
    out[BN*4+b]=a;
  }
}

extern "C" void kernel_launch(void* const* d_in, const int* in_sizes, int n_in,
                              void* d_out, int out_size)
{
  const float* x    =(const float*)d_in[0];
  const float* ipw  =(const float*)d_in[1];   // (2,6,96)
  const float* cw   =(const float*)d_in[2];   // (2,48,16)
  const float* cb   =(const float*)d_in[3];   // (2,48)
  const float* xpw  =(const float*)d_in[4];   // (2,48,65)
  const float* dtw  =(const float*)d_in[5];   // (2,1,48)
  const float* dtb  =(const float*)d_in[6];   // (2,48)
  const float* alog =(const float*)d_in[7];   // (2,48,32)
  const float* Dw   =(const float*)d_in[8];   // (2,48)
  const float* nw   =(const float*)d_in[9];   // (2,6)
  const float* ow   =(const float*)d_in[10];  // (1,48,6)
  const float* fcw  =(const float*)d_in[11];
  const float* fcb  =(const float*)d_in[12];
  const float* clsw =(const float*)d_in[13];
  const float* clsb =(const float*)d_in[14];
  const float* regw =(const float*)d_in[15];
  const float* regb =(const float*)d_in[16];
  float* out = (float*)d_out;

  k_pre1 <<<BN*NT, 128>>>(x, ipw, cw, cb, xpw, dtw, dtb, nw);
  k_scan1<<<BN*12, dim3(32,4)>>>(alog, Dw);
  k_mid  <<<BN*NT, 128>>>(x, ow, ipw+6*96, cw+48*16, cb+48, xpw+48*65, dtw+48, dtb+48, nw+DM);
  k_scan2<<<BN*12, dim3(32,4)>>>(alog+48*32, Dw+48);
  k_final<<<1, 256>>>(fcw, fcb, clsw, clsb, regw, regb, out);
}

// round 4
// speedup vs baseline: 1.7641x; 1.7641x over previous
#include <cuda_runtime.h>

#define BN 16
#define LEN 1024
#define DM 6
#define EDx 48
#define NS 32
#define NT 16        // time tiles per sequence
#define TT 64        // timesteps per tile
#define HALO 15
#define NCH 16       // scan chunks
#define CL 64        // timesteps per chunk
#define EPSV 1e-5f

// ---------------- scratch (device globals; no allocations) ----------------
__device__ float2 g_P [2][BN*EDx*LEN];       // {delta, xs} per (b,e,t)
__device__ float  g_BC[2][BN*LEN*2*NS];      // interleaved {B_n, C_n}
__device__ float  g_z [2][BN*LEN*EDx];       // gate z
__device__ float  g_y1[BN*EDx*LEN];          // layer-1 scan output (incl D*xs)
__device__ float2 g_seg[BN*EDx*NCH*NS];      // per-chunk affine summary {A, H}
__device__ float  g_hin[BN*EDx*NCH*NS];      // per-chunk initial h
__device__ float  g_fi[BN*EDx];              // features into head

__device__ __forceinline__ float ex2f(float x){ float r; asm("ex2.approx.ftz.f32 %0, %1;":"=f"(r):"f"(x)); return r; }
__device__ __forceinline__ float siluf(float x){ return x/(1.f+__expf(-x)); }
__device__ __forceinline__ float softplusf(float x){ return (x>20.f)? x : log1pf(__expf(x)); }
__device__ __forceinline__ float warpsum(float v){
  #pragma unroll
  for(int o=16;o;o>>=1) v += __shfl_xor_sync(0xffffffffu, v, o);
  return v;
}

struct SmemPre {
  float u [(TT+HALO)*DM];     // rmsnorm'ed input
  float sp[(TT+HALO)*EDx];    // pre-conv xs (also reused as gated-y staging in k_mid)
  float xc[EDx*TT];           // post-conv silu(xs), TRANSPOSED [e][t]
  float cw[EDx*16];           // conv weights
  float wx[EDx*65];           // x_proj weights
  float dlt[TT];              // raw dt
};

// Shared tail: xs_pre -> conv -> silu -> x_proj -> softplus(delta); emits P/BC/z.
template<int LAYER>
__device__ void pre_tail(SmemPre& s, int b, int t0,
    const float* __restrict__ Win, const float* __restrict__ convw,
    const float* __restrict__ convb, const float* __restrict__ Wx,
    const float* __restrict__ dtw, const float* __restrict__ dtb)
{
  const int tid = threadIdx.x;
  for (int i=tid;i<EDx*16;i+=128) s.cw[i]=convw[i];
  for (int i=tid;i<EDx*65;i+=128) s.wx[i]=Wx[i];
  __syncthreads();
  // xs_pre = u @ Win[:, :48]  (halo positions included)
  for (int idx=tid; idx<(TT+HALO)*EDx; idx+=128){
    int i=idx/EDx, c=idx-i*EDx;
    const float* u=&s.u[i*DM];
    float a=0.f;
    #pragma unroll
    for(int d=0;d<DM;d++) a = fmaf(u[d], __ldg(&Win[d*96+c]), a);
    s.sp[idx]=a;
  }
  // z = u @ Win[:, 48:]  (tile positions only)
  for (int idx=tid; idx<TT*EDx; idx+=128){
    int j=idx/EDx, c=idx-j*EDx;
    const float* u=&s.u[(j+HALO)*DM];
    float a=0.f;
    #pragma unroll
    for(int d=0;d<DM;d++) a = fmaf(u[d], __ldg(&Win[d*96+48+c]), a);
    g_z[LAYER][(b*LEN + t0 + j)*EDx + c] = a;
  }
  __syncthreads();
  // causal depthwise conv (16 taps) + bias + silu  -> transposed xc[e][t]
  for (int idx=tid; idx<TT*EDx; idx+=128){
    int j=idx/EDx, c=idx-j*EDx;
    float a=convb[c];
    #pragma unroll
    for(int k=0;k<16;k++) a = fmaf(s.cw[c*16+k], s.sp[(j+k)*EDx+c], a);
    s.xc[c*TT+j]=siluf(a);
  }
  __syncthreads();
  // x_proj: 48 -> 65 (dt | B | C). thread = (j, half); xr cached in registers.
  {
    int j = tid >> 1, half = tid & 1;
    float xr[EDx];
    #pragma unroll
    for(int c=0;c<EDx;c++) xr[c]=s.xc[c*TT+j];
    int t=t0+j;
    int m0 = half? 33:0, m1 = half? 65:33;
    for(int m=m0;m<m1;m++){
      float a=0.f;
      #pragma unroll
      for(int c=0;c<EDx;c++) a=fmaf(xr[c], s.wx[c*65+m], a);
      if(m==0)       s.dlt[j]=a;
      else if(m<33)  g_BC[LAYER][(b*LEN+t)*(2*NS) + (m-1 )*2    ] = a;
      else           g_BC[LAYER][(b*LEN+t)*(2*NS) + (m-33)*2 + 1] = a;
    }
  }
  __syncthreads();
  // delta = softplus(dlt*dt_w + dt_b); pack {delta, xs} per stream (B,ED,L)
  for (int idx=tid; idx<EDx*TT; idx+=128){
    int e=idx/TT, j=idx-e*TT;
    float delta = softplusf(fmaf(s.dlt[j], dtw[e], dtb[e]));
    g_P[LAYER][(b*EDx+e)*LEN + t0 + j] = make_float2(delta, s.xc[e*TT+j]);
  }
}

__global__ void __launch_bounds__(128) k_pre1(const float* __restrict__ x,
   const float* __restrict__ ip, const float* __restrict__ cw, const float* __restrict__ cb,
   const float* __restrict__ xp, const float* __restrict__ dtw, const float* __restrict__ dtb,
   const float* __restrict__ nw)
{
  __shared__ SmemPre s;
  int b = blockIdx.x >> 4, t0 = (blockIdx.x & 15) * TT;
  int tid = threadIdx.x;
  for (int i=tid;i<TT+HALO;i+=128){
    int t=t0-HALO+i;
    if (t>=0){
      float v[DM]; float ss=0.f;
      #pragma unroll
      for(int d=0;d<DM;d++){ v[d]=x[(b*LEN+t)*DM+d]; ss=fmaf(v[d],v[d],ss); }
      float r = rsqrtf(ss*(1.f/DM)+EPSV);
      #pragma unroll
      for(int d=0;d<DM;d++) s.u[i*DM+d]=v[d]*r*nw[d];
    } else {
      #pragma unroll
      for(int d=0;d<DM;d++) s.u[i*DM+d]=0.f;
    }
  }
  pre_tail<0>(s,b,t0, ip,cw,cb,xp,dtw,dtb);
}

// post-layer1 (gate, out_proj, residual) fused with full layer-2 pre
__global__ void __launch_bounds__(128) k_mid(const float* __restrict__ x,
   const float* __restrict__ ow,
   const float* __restrict__ ip, const float* __restrict__ cw, const float* __restrict__ cb,
   const float* __restrict__ xp, const float* __restrict__ dtw, const float* __restrict__ dtb,
   const float* __restrict__ nw)
{
  __shared__ SmemPre s;
  int b = blockIdx.x >> 4, t0 = (blockIdx.x & 15) * TT;
  int tid = threadIdx.x;
  // Stage A: cooperative coalesced gather of gated y into s.sp (aliased as gg[e][i])
  for (int idx=tid; idx<EDx*(TT+HALO); idx+=128){
    int e=idx/(TT+HALO), i=idx-e*(TT+HALO);
    int t=t0-HALO+i;
    float g=0.f;
    if (t>=0){
      float yv = g_y1[(b*EDx+e)*LEN + t];
      float zv = g_z[0][(b*LEN+t)*EDx + e];
      g = yv*siluf(zv);
    }
    s.sp[e*(TT+HALO)+i]=g;
  }
  __syncthreads();
  // Stage B: h = x + g @ out_proj; rmsnorm -> u
  for (int i=tid;i<TT+HALO;i+=128){
    int t=t0-HALO+i;
    if (t>=0){
      float hd[DM];
      #pragma unroll
      for(int d=0;d<DM;d++) hd[d]=x[(b*LEN+t)*DM+d];   // residual
      for(int e=0;e<EDx;e++){
        float g = s.sp[e*(TT+HALO)+i];
        #pragma unroll
        for(int d=0;d<DM;d++) hd[d] = fmaf(g, __ldg(&ow[e*DM+d]), hd[d]);
      }
      float ss=0.f;
      #pragma unroll
      for(int d=0;d<DM;d++) ss = fmaf(hd[d],hd[d],ss);
      float r = rsqrtf(ss*(1.f/DM)+EPSV);
      #pragma unroll
      for(int d=0;d<DM;d++) s.u[i*DM+d]=hd[d]*r*nw[d];
    } else {
      #pragma unroll
      for(int d=0;d<DM;d++) s.u[i*DM+d]=0.f;
    }
  }
  __syncthreads();   // s.sp about to be overwritten by pre_tail
  pre_tail<1>(s,b,t0, ip,cw,cb,xp,dtw,dtb);
}

// Phase A: per-chunk affine summary. warp = (b,e,chunk), lane = n.
template<int LAYER>
__global__ void __launch_bounds__(128) k_segA(const float* __restrict__ alog)
{
  int bid = blockIdx.x;
  int b = bid / (NCH*12);
  int rem = bid - b*(NCH*12);
  int c = rem / 12;
  int e = (rem - c*12)*4 + threadIdx.y;
  int lane = threadIdx.x;
  float acoef = -__expf(alog[e*NS+lane]) * 1.4426950408889634f;
  const float2* __restrict__ P  = &g_P[LAYER][(b*EDx+e)*LEN + c*CL];
  const float2* __restrict__ BC = (const float2*)&g_BC[LAYER][((size_t)b*LEN + c*CL)*(2*NS)] + lane;
  float A=1.f, H=0.f;
  #pragma unroll 8
  for(int t=0;t<CL;t++){
    float2 p  = P[t];
    float2 bc = BC[(size_t)t*NS];
    float a = ex2f(p.x*acoef);
    H = fmaf(a, H, (p.x*p.y)*bc.x);
    A *= a;
  }
  g_seg[((b*EDx+e)*NCH + c)*NS + lane] = make_float2(A,H);
}

// Phase B (layer 1): sequential combine of chunk summaries -> per-chunk initial h
__global__ void __launch_bounds__(128) k_comb1()
{
  int b = blockIdx.x / 12;
  int e = (blockIdx.x % 12)*4 + threadIdx.y;
  int lane = threadIdx.x;
  size_t base = ((size_t)(b*EDx+e))*NCH*NS + lane;
  float h=0.f;
  #pragma unroll
  for(int c=0;c<NCH;c++){
    g_hin[base + c*NS] = h;
    float2 s = g_seg[base + c*NS];
    h = fmaf(s.x, h, s.y);
  }
}

// Phase C (layer 1): replay chunk from its initial h, emit y (+ D*xs).
__global__ void __launch_bounds__(128) k_segC(const float* __restrict__ alog,
                                              const float* __restrict__ Dw)
{
  int bid = blockIdx.x;
  int b = bid / (NCH*12);
  int rem = bid - b*(NCH*12);
  int c = rem / 12;
  int e = (rem - c*12)*4 + threadIdx.y;
  int lane = threadIdx.x;
  float acoef = -__expf(alog[e*NS+lane]) * 1.4426950408889634f;
  float De = Dw[e];
  const float2* __restrict__ P  = &g_P[0][(b*EDx+e)*LEN + c*CL];
  const float2* __restrict__ BC = (const float2*)&g_BC[0][((size_t)b*LEN + c*CL)*(2*NS)] + lane;
  float* __restrict__ Y = &g_y1[(b*EDx+e)*LEN + c*CL];
  float h = g_hin[((size_t)(b*EDx+e))*NCH*NS + c*NS + lane];
  float ybuf=0.f;
  for (int t0=0;t0<CL;t0+=32){
    #pragma unroll
    for(int j=0;j<32;j++){
      int t=t0+j;
      float2 p  = P[t];
      float2 bc = BC[(size_t)t*NS];
      float a = ex2f(p.x*acoef);
      h = fmaf(a, h, (p.x*p.y)*bc.x);
      float sv = warpsum(h*bc.y);
      if (j==lane) ybuf = fmaf(De, p.y, sv);
    }
    Y[t0+lane]=ybuf;               // coalesced 128B store per warp
  }
}

// Phase B (layer 2): combine to final h, compute feature directly.
__global__ void __launch_bounds__(128) k_comb2(const float* __restrict__ Dw)
{
  int b = blockIdx.x / 12;
  int e = (blockIdx.x % 12)*4 + threadIdx.y;
  int lane = threadIdx.x;
  size_t base = ((size_t)(b*EDx+e))*NCH*NS + lane;
  float h=0.f;
  #pragma unroll
  for(int c=0;c<NCH;c++){
    float2 s = g_seg[base + c*NS];
    h = fmaf(s.x, h, s.y);
  }
  int t = LEN-1;
  float2 p  = g_P[1][(b*EDx+e)*LEN + t];
  float2 bc = ((const float2*)&g_BC[1][((size_t)b*LEN+t)*(2*NS)])[lane];
  float sv = warpsum(h*bc.y);
  if (lane==0){
    float y  = fmaf(Dw[e], p.y, sv);
    float zv = g_z[1][(b*LEN+t)*EDx + e];
    g_fi[b*EDx+e] = y*siluf(zv);
  }
}

__global__ void __launch_bounds__(256) k_final(
   const float* __restrict__ fcw, const float* __restrict__ fcb,
   const float* __restrict__ clsw, const float* __restrict__ clsb,
   const float* __restrict__ regw, const float* __restrict__ regb,
   float* __restrict__ out)
{
  __shared__ float feat[BN*EDx];
  int tid = threadIdx.x;
  for (int idx=tid; idx<BN*EDx; idx+=256){
    int b=idx/EDx, j=idx-b*EDx;
    float a=fcb[j];
    #pragma unroll 12
    for(int e=0;e<EDx;e++) a = fmaf(g_fi[b*EDx+e], fcw[e*EDx+j], a);
    feat[idx] = fmaxf(a, 0.f);
  }
  __syncthreads();
  if (tid < BN*4){
    int b=tid>>2, k=tid&3;
    float a=clsb[k];
    #pragma unroll 12
    for(int j=0;j<EDx;j++) a = fmaf(feat[b*EDx+j], clsw[j*4+k], a);
    out[b*4+k]=a;
  } else if (tid < BN*4 + BN){
    int b=tid-BN*4;
    float a=regb[0];
    #pragma unroll 12
    for(int j=0;j<EDx;j++) a = fmaf(feat[b*EDx+j], regw[j], a);
    out[BN*4+b]=a;
  }
}

extern "C" void kernel_launch(void* const* d_in, const int* in_sizes, int n_in,
                              void* d_out, int out_size)
{
  const float* x    =(const float*)d_in[0];
  const float* ipw  =(const float*)d_in[1];   // (2,6,96)
  const float* cw   =(const float*)d_in[2];   // (2,48,16)
  const float* cb   =(const float*)d_in[3];   // (2,48)
  const float* xpw  =(const float*)d_in[4];   // (2,48,65)
  const float* dtw  =(const float*)d_in[5];   // (2,1,48)
  const float* dtb  =(const float*)d_in[6];   // (2,48)
  const float* alog =(const float*)d_in[7];   // (2,48,32)
  const float* Dw   =(const float*)d_in[8];   // (2,48)
  const float* nw   =(const float*)d_in[9];   // (2,6)
  const float* ow   =(const float*)d_in[10];  // (1,48,6)
  const float* fcw  =(const float*)d_in[11];
  const float* fcb  =(const float*)d_in[12];
  const float* clsw =(const float*)d_in[13];
  const float* clsb =(const float*)d_in[14];
  const float* regw =(const float*)d_in[15];
  const float* regb =(const float*)d_in[16];
  float* out = (float*)d_out;

  k_pre1 <<<BN*NT, 128>>>(x, ipw, cw, cb, xpw, dtw, dtb, nw);
  k_segA<0><<<BN*NCH*12, dim3(32,4)>>>(alog);
  k_comb1  <<<BN*12, dim3(32,4)>>>();
  k_segC   <<<BN*NCH*12, dim3(32,4)>>>(alog, Dw);
  k_mid  <<<BN*NT, 128>>>(x, ow, ipw+6*96, cw+48*16, cb+48, xpw+48*65, dtw+48, dtb+48, nw+DM);
  k_segA<1><<<BN*NCH*12, dim3(32,4)>>>(alog+48*32);
  k_comb2  <<<BN*12, dim3(32,4)>>>(Dw+48);
  k_final<<<1, 256>>>(fcw, fcb, clsw, clsb, regw, regb, out);
}

// round 5
// speedup vs baseline: 2.1814x; 1.2365x over previous
#include <cuda_runtime.h>

#define BN 16
#define LEN 1024
#define DM 6
#define EDx 48
#define NS 32
#define NT 16        // 64-wide time tiles per sequence
#define TT 64
#define HALO 15
#define NCH 32       // scan chunks
#define CL 32        // steps per chunk
#define EPSV 1e-5f
#define L2E 1.4426950408889634f

// ---------------- scratch (device globals; no allocations) ----------------
__device__ float2 g_P0 [BN*EDx*LEN];      // layer-1 {delta, xs} per (b,e,t)
__device__ float2 g_BC0[BN*LEN*NS];       // layer-1 {B_n, C_n} per (b,t,n)
__device__ float  g_z0 [BN*EDx*LEN];      // layer-1 gate z, (b,e,t) layout
__device__ float  g_y1 [BN*EDx*LEN];      // layer-1 scan output (incl D*xs)
__device__ float2 g_seg0[BN*EDx*NCH*NS];  // per-chunk affine summary {A, H}
__device__ float2 g_seg1[BN*EDx*NCH*NS];
__device__ float  g_lastC [BN*NS];        // layer-2 C at t=L-1
__device__ float  g_lastxs[BN*EDx];       // layer-2 xs at t=L-1
__device__ float  g_lastz [BN*EDx];       // layer-2 z  at t=L-1
__device__ float  g_fi[BN*EDx];           // features into head
__device__ unsigned g_ctr;

__device__ __forceinline__ float ex2f(float x){ float r; asm("ex2.approx.ftz.f32 %0, %1;":"=f"(r):"f"(x)); return r; }
__device__ __forceinline__ float siluf(float x){ return x/(1.f+__expf(-x)); }
__device__ __forceinline__ float softplusf(float x){ return (x>20.f)? x : log1pf(__expf(x)); }
__device__ __forceinline__ float warpsum(float v){
  #pragma unroll
  for(int o=16;o;o>>=1) v += __shfl_xor_sync(0xffffffffu, v, o);
  return v;
}
// Merge two lane-distributed partial-sum vectors: bit0 lanes keep a's pair-sums,
// bit1 lanes keep b's. After masks 1,2,4,8,16 lane j holds full sum of vector j.
__device__ __forceinline__ float mergef(float a, float b, int mask){
  int hi = threadIdx.x & mask;
  float t = hi ? b : a;
  float u = hi ? a : b;
  return t + __shfl_xor_sync(0xffffffffu, u, mask);
}

// shared pool offsets (floats)
#define S_U    0      // 474:  u[(79)*6]
#define S_DLT  474    // 64
#define S_DSUM 538    // 96:   sum(delta) per (e, halfchunk)
#define S_CW   640    // 768:  conv w
#define S_XC   1408   // 3120: xs post-conv, [e*65 + t] (padded)
#define S_SB   4528   // 2112: B, [t*33 + n] (padded)
#define S_SP   6640   // 3792: pre-xs -> wx -> delta[e*64+t]; gg in layer 1
#define S_TOT  10432  // 41.7 KB

// Fused: (rmsnorm | gated out_proj+residual+rmsnorm) -> in_proj -> conv -> silu
//        -> x_proj -> softplus(delta) -> per-chunk segA summaries.
template<int LAYER>
__global__ void __launch_bounds__(256) k_preA(
  const float* __restrict__ x,   const float* __restrict__ Win,
  const float* __restrict__ convw, const float* __restrict__ convb,
  const float* __restrict__ Wx,  const float* __restrict__ dtw,
  const float* __restrict__ dtb, const float* __restrict__ alog,
  const float* __restrict__ nw,  const float* __restrict__ ow)
{
  __shared__ float sm[S_TOT];
  const int tid = threadIdx.x;
  const int b = blockIdx.x >> 4, tile = blockIdx.x & 15, t0 = tile*TT;

  for(int i=tid;i<EDx*16;i+=256) sm[S_CW+i]=convw[i];

  if (LAYER==0){
    for(int i=tid;i<TT+HALO;i+=256){
      int t=t0-HALO+i;
      if(t>=0){
        float v[DM]; float ss=0.f;
        #pragma unroll
        for(int d=0;d<DM;d++){ v[d]=x[(b*LEN+t)*DM+d]; ss=fmaf(v[d],v[d],ss); }
        float r=rsqrtf(ss*(1.f/DM)+EPSV);
        #pragma unroll
        for(int d=0;d<DM;d++) sm[S_U+i*DM+d]=v[d]*r*nw[d];
      } else {
        #pragma unroll
        for(int d=0;d<DM;d++) sm[S_U+i*DM+d]=0.f;
      }
    }
  } else {
    // gather gated y (coalesced: both g_y1 and g_z0 are (b,e,t))
    for(int idx=tid; idx<EDx*(TT+HALO); idx+=256){
      int e=idx/(TT+HALO), i=idx-e*(TT+HALO); int t=t0-HALO+i;
      float g=0.f;
      if(t>=0){
        float yv=g_y1[(b*EDx+e)*LEN+t];
        float zv=g_z0[(b*EDx+e)*LEN+t];
        g=yv*siluf(zv);
      }
      sm[S_SP+e*(TT+HALO)+i]=g;
    }
    __syncthreads();
    for(int i=tid;i<TT+HALO;i+=256){
      int t=t0-HALO+i;
      if(t>=0){
        float hd[DM];
        #pragma unroll
        for(int d=0;d<DM;d++) hd[d]=x[(b*LEN+t)*DM+d];
        for(int e=0;e<EDx;e++){
          float g=sm[S_SP+e*(TT+HALO)+i];
          #pragma unroll
          for(int d=0;d<DM;d++) hd[d]=fmaf(g, __ldg(&ow[e*DM+d]), hd[d]);
        }
        float ss=0.f;
        #pragma unroll
        for(int d=0;d<DM;d++) ss=fmaf(hd[d],hd[d],ss);
        float r=rsqrtf(ss*(1.f/DM)+EPSV);
        #pragma unroll
        for(int d=0;d<DM;d++) sm[S_U+i*DM+d]=hd[d]*r*nw[d];
      } else {
        #pragma unroll
        for(int d=0;d<DM;d++) sm[S_U+i*DM+d]=0.f;
      }
    }
  }
  __syncthreads();
  // pre-conv xs = u @ Win[:, :48]   (SP[i*48+c])
  for(int idx=tid; idx<(TT+HALO)*EDx; idx+=256){
    int i=idx/EDx, c=idx-i*EDx;
    const float* u=&sm[S_U+i*DM];
    float a=0.f;
    #pragma unroll
    for(int d=0;d<DM;d++) a=fmaf(u[d], __ldg(&Win[d*96+c]), a);
    sm[S_SP+idx]=a;
  }
  // z = u @ Win[:, 48:]
  if (LAYER==0){
    for(int idx=tid; idx<TT*EDx; idx+=256){
      int e=idx>>6, j=idx&63;
      const float* u=&sm[S_U+(j+HALO)*DM];
      float a=0.f;
      #pragma unroll
      for(int d=0;d<DM;d++) a=fmaf(u[d], __ldg(&Win[d*96+48+e]), a);
      g_z0[(b*EDx+e)*LEN + t0 + j]=a;
    }
  } else {
    if (tile==15 && tid<EDx){
      const float* u=&sm[S_U+78*DM];
      float a=0.f;
      #pragma unroll
      for(int d=0;d<DM;d++) a=fmaf(u[d], __ldg(&Win[d*96+48+tid]), a);
      g_lastz[b*EDx+tid]=a;
    }
  }
  __syncthreads();
  // causal depthwise conv + bias + silu -> XC[c*65+j]
  for(int idx=tid; idx<TT*EDx; idx+=256){
    int j=idx/EDx, c=idx-j*EDx;
    float a=convb[c];
    #pragma unroll
    for(int k=0;k<16;k++) a=fmaf(sm[S_CW+c*16+k], sm[S_SP+(j+k)*EDx+c], a);
    sm[S_XC+c*65+j]=siluf(a);
  }
  __syncthreads();
  // load x_proj weights into SP (pre-xs dead)
  for(int i=tid;i<EDx*65;i+=256) sm[S_SP+i]=Wx[i];
  __syncthreads();
  // x_proj: thread = (j, quarter)
  {
    int j=tid>>2, q=tid&3;
    float xr[EDx];
    #pragma unroll
    for(int c=0;c<EDx;c++) xr[c]=sm[S_XC+c*65+j];
    int t=t0+j;
    int m0 = q? (16*q+1):0;
    int m1 = 16*q+17;
    for(int m=m0;m<m1;m++){
      float a=0.f;
      #pragma unroll
      for(int c=0;c<EDx;c++) a=fmaf(xr[c], sm[S_SP+c*65+m], a);
      if(m==0) sm[S_DLT+j]=a;
      else if(m<=32){
        sm[S_SB+j*33+(m-1)]=a;
        if(LAYER==0) ((float*)g_BC0)[((size_t)b*LEN+t)*(2*NS) + (m-1)*2]=a;
      } else {
        if(LAYER==0) ((float*)g_BC0)[((size_t)b*LEN+t)*(2*NS) + (m-33)*2+1]=a;
        else if(tile==15 && j==63) g_lastC[b*NS+(m-33)]=a;
      }
    }
  }
  __syncthreads();
  // delta = softplus(...); store into SP[e*64+j] (wx dead); per-halfchunk sums
  for(int idx=tid; idx<EDx*TT; idx+=256){
    int e=idx>>6, j=idx&63;
    float delta = softplusf(fmaf(sm[S_DLT+j], dtw[e], dtb[e]));
    float s = warpsum(delta);
    if((j&31)==0) sm[S_DSUM+e*2+(j>>5)]=s;
    sm[S_SP+e*64+j]=delta;
    if(LAYER==0)
      g_P0[(b*EDx+e)*LEN + t0 + j] = make_float2(delta, sm[S_XC+e*65+j]);
  }
  if (LAYER==1 && tile==15 && tid<EDx) g_lastxs[b*EDx+tid]=sm[S_XC+tid*65+63];
  __syncthreads();
  // segA: warp-task = (halfchunk c, e); summary {A = ex2(acoef*sum_delta), H}
  {
    int warpId=tid>>5, n=tid&31;
    for(int task=warpId; task<96; task+=8){
      int c = task>=48 ? 1:0; int e = task - c*48;
      float acoef = -__expf(alog[e*NS+n])*L2E;
      float H=0.f;
      #pragma unroll
      for(int s=0;s<CL;s++){
        int gt=c*CL+s;
        float dl=sm[S_SP+e*64+gt];
        float xs=sm[S_XC+e*65+gt];
        float Bv=sm[S_SB+gt*33+n];
        float a=ex2f(dl*acoef);
        H=fmaf(a,H,(dl*xs)*Bv);
      }
      float A=ex2f(acoef*sm[S_DSUM+e*2+c]);
      float2* seg = (LAYER==0)? g_seg0 : g_seg1;
      seg[((b*EDx+e)*NCH + (tile*2+c))*NS + n]=make_float2(A,H);
    }
  }
}

// Layer-1 replay: inline chunk-prefix lookback + merge-tree y reduction.
__global__ void __launch_bounds__(128) k_segC(const float* __restrict__ alog,
                                              const float* __restrict__ Dw)
{
  int blk=blockIdx.x;
  int b = blk/(NCH*12);
  int rem = blk - b*(NCH*12);
  int c = rem/12;
  int e = (rem - c*12)*4 + threadIdx.y;
  int n = threadIdx.x;
  float acoef = -__expf(alog[e*NS+n])*L2E;
  // lookback over preceding chunk summaries
  const float2* S = &g_seg0[((b*EDx+e)*NCH)*NS + n];
  float h=0.f;
  #pragma unroll 4
  for(int cc=0;cc<c;cc++){ float2 s=S[cc*NS]; h=fmaf(s.x,h,s.y); }
  const float2* P  = &g_P0[(b*EDx+e)*LEN + c*CL];
  const float2* BC = &g_BC0[((size_t)b*LEN + c*CL)*NS + n];
  float acc0,acc1,acc2,acc3,acc4,res=0.f;
  #pragma unroll
  for(int j=0;j<CL;j++){
    float2 p  = P[j];
    float2 bc = BC[(size_t)j*NS];
    float a = ex2f(p.x*acoef);
    h = fmaf(a, h, (p.x*p.y)*bc.x);
    float cur = h*bc.y;
    if (j&1){ cur=mergef(acc0,cur,1);
      if(j&2){ cur=mergef(acc1,cur,2);
        if(j&4){ cur=mergef(acc2,cur,4);
          if(j&8){ cur=mergef(acc3,cur,8);
            if(j&16){ res=mergef(acc4,cur,16); }
            else acc4=cur; }
          else acc3=cur; }
        else acc2=cur; }
      else acc1=cur; }
    else acc0=cur;
  }
  float2 pl = P[n];
  g_y1[(b*EDx+e)*LEN + c*CL + n] = fmaf(Dw[e], pl.y, res);
}

// Layer-2 final combine + feature + fused head (last-block pattern).
__global__ void __launch_bounds__(128) k_comb2final(
   const float* __restrict__ Dw,
   const float* __restrict__ fcw, const float* __restrict__ fcb,
   const float* __restrict__ clsw, const float* __restrict__ clsb,
   const float* __restrict__ regw, const float* __restrict__ regb,
   float* __restrict__ out)
{
  __shared__ float feat[BN*EDx];
  __shared__ int isLast;
  int b = blockIdx.x/12;
  int e = (blockIdx.x%12)*4 + threadIdx.y;
  int n = threadIdx.x;
  int tid = threadIdx.y*32+n;
  const float2* S = &g_seg1[((b*EDx+e)*NCH)*NS + n];
  float h=0.f;
  #pragma unroll
  for(int cc=0;cc<NCH;cc++){ float2 s=S[cc*NS]; h=fmaf(s.x,h,s.y); }
  float sv = warpsum(h * g_lastC[b*NS+n]);
  if(n==0){
    float y = fmaf(Dw[e], g_lastxs[b*EDx+e], sv);
    g_fi[b*EDx+e] = y * siluf(g_lastz[b*EDx+e]);
  }
  __threadfence();
  __syncthreads();
  if(tid==0){ unsigned old=atomicAdd(&g_ctr,1u); isLast = (old==(unsigned)(gridDim.x-1)); }
  __syncthreads();
  if(!isLast) return;
  if(tid==0) g_ctr=0;
  __threadfence();
  for(int idx=tid; idx<BN*EDx; idx+=128){
    int bb=idx/EDx, j=idx-bb*EDx;
    float a=fcb[j];
    #pragma unroll 12
    for(int ee=0;ee<EDx;ee++) a=fmaf(g_fi[bb*EDx+ee], fcw[ee*EDx+j], a);
    feat[idx]=fmaxf(a,0.f);
  }
  __syncthreads();
  if(tid<BN*4){
    int bb=tid>>2,k=tid&3;
    float a=clsb[k];
    #pragma unroll 12
    for(int j=0;j<EDx;j++) a=fmaf(feat[bb*EDx+j], clsw[j*4+k], a);
    out[bb*4+k]=a;
  } else if(tid<BN*4+BN){
    int bb=tid-BN*4;
    float a=regb[0];
    #pragma unroll 12
    for(int j=0;j<EDx;j++) a=fmaf(feat[bb*EDx+j], regw[j], a);
    out[BN*4+bb]=a;
  }
}

extern "C" void kernel_launch(void* const* d_in, const int* in_sizes, int n_in,
                              void* d_out, int out_size)
{
  const float* x    =(const float*)d_in[0];
  const float* ipw  =(const float*)d_in[1];   // (2,6,96)
  const float* cw   =(const float*)d_in[2];   // (2,48,16)
  const float* cb   =(const float*)d_in[3];   // (2,48)
  const float* xpw  =(const float*)d_in[4];   // (2,48,65)
  const float* dtw  =(const float*)d_in[5];   // (2,1,48)
  const float* dtb  =(const float*)d_in[6];   // (2,48)
  const float* alog =(const float*)d_in[7];   // (2,48,32)
  const float* Dw   =(const float*)d_in[8];   // (2,48)
  const float* nw   =(const float*)d_in[9];   // (2,6)
  const float* ow   =(const float*)d_in[10];  // (1,48,6)
  const float* fcw  =(const float*)d_in[11];
  const float* fcb  =(const float*)d_in[12];
  const float* clsw =(const float*)d_in[13];
  const float* clsb =(const float*)d_in[14];
  const float* regw =(const float*)d_in[15];
  const float* regb =(const float*)d_in[16];
  float* out = (float*)d_out;

  k_preA<0><<<BN*NT, 256>>>(x, ipw, cw, cb, xpw, dtw, dtb, alog, nw, ow);
  k_segC   <<<BN*NCH*12, dim3(32,4)>>>(alog, Dw);
  k_preA<1><<<BN*NT, 256>>>(x, ipw+6*96, cw+768, cb+48, xpw+3120,
                            dtw+48, dtb+48, alog+1536, nw+DM, ow);
  k_comb2final<<<BN*12, dim3(32,4)>>>(Dw+48, fcw, fcb, clsw, clsb, regw, regb, out);
}

// round 6
// speedup vs baseline: 2.3729x; 1.0878x over previous
#include <cuda_runtime.h>

#define BN 16
#define LEN 1024
#define DM 6
#define EDx 48
#define NS 32
#define NT 16        // 64-wide time tiles per sequence
#define TT 64
#define HALO 15
#define NCH 32       // scan chunks
#define CL 32        // steps per chunk
#define EPSV 1e-5f
#define L2E 1.4426950408889634f

// ---------------- scratch (device globals; no allocations) ----------------
__device__ float2 g_P0 [BN*EDx*LEN];      // layer-1 {delta, xs} per (b,e,t)
__device__ float2 g_BC0[BN*LEN*NS];       // layer-1 {B_n, C_n} per (b,t,n)
__device__ float  g_z0 [BN*EDx*LEN];      // layer-1 gate z, (b,e,t) layout
__device__ float  g_y1 [BN*EDx*LEN];      // layer-1 scan output (incl D*xs)
__device__ float2 g_half0[BN*EDx*NT*NS];  // layer-1 first-halfchunk summaries
__device__ float2 g_tile0[BN*EDx*NT*NS];  // layer-1 tile summaries {A, H}
__device__ float2 g_tile1[BN*EDx*NT*NS];  // layer-2 tile summaries
__device__ float  g_lastC [BN*NS];        // layer-2 C at t=L-1
__device__ float  g_lastxs[BN*EDx];       // layer-2 xs at t=L-1
__device__ float  g_lastz [BN*EDx];       // layer-2 z  at t=L-1
__device__ float  g_fi[BN*EDx];           // features into head
__device__ unsigned g_ctr;

__device__ __forceinline__ float ex2f(float x){ float r; asm("ex2.approx.ftz.f32 %0, %1;":"=f"(r):"f"(x)); return r; }
__device__ __forceinline__ float siluf(float x){ return x/(1.f+__expf(-x)); }
__device__ __forceinline__ float softplusf(float x){ return (x>20.f)? x : log1pf(__expf(x)); }
__device__ __forceinline__ float warpsum(float v){
  #pragma unroll
  for(int o=16;o;o>>=1) v += __shfl_xor_sync(0xffffffffu, v, o);
  return v;
}
// Merge two lane-distributed partial-sum vectors. After masks 1,2,4,8,16 the
// lane j holds the full sum of vector j.
__device__ __forceinline__ float mergef(float a, float b, int mask){
  int hi = threadIdx.x & mask;
  float t = hi ? b : a;
  float u = hi ? a : b;
  return t + __shfl_xor_sync(0xffffffffu, u, mask);
}

// shared pool offsets (floats)
#define S_U    0      // 474:  u[(79)*6]
#define S_DLT  474    // 64
#define S_DSUM 538    // 96:   sum(delta) per (e, halfchunk)
#define S_CW   640    // 768:  conv w
#define S_OW   1408   // 288:  out_proj w (layer 1 path)
#define S_XC   1696   // 3120: xs post-conv, [e*65 + t] (padded)
#define S_SB   4816   // 2112: B, [t*33 + n] (padded)
#define S_SP   6928   // 3792: pre-xs -> wx -> delta[e*64+t]; gg staging
#define S_TOT  10720  // 42.9 KB

// Fused: (rmsnorm | gated out_proj+residual+rmsnorm) -> in_proj -> conv -> silu
//        -> x_proj -> softplus(delta) -> halfchunk + tile scan summaries.
template<int LAYER>
__global__ void __launch_bounds__(256) k_preA(
  const float* __restrict__ x,   const float* __restrict__ Win,
  const float* __restrict__ convw, const float* __restrict__ convb,
  const float* __restrict__ Wx,  const float* __restrict__ dtw,
  const float* __restrict__ dtb, const float* __restrict__ alog,
  const float* __restrict__ nw,  const float* __restrict__ ow)
{
  __shared__ float sm[S_TOT];
  const int tid = threadIdx.x;
  const int b = blockIdx.x >> 4, tile = blockIdx.x & 15, t0 = tile*TT;

  for(int i=tid;i<EDx*16;i+=256) sm[S_CW+i]=convw[i];
  if (LAYER==1) for(int i=tid;i<EDx*DM;i+=256) sm[S_OW+i]=ow[i];

  if (LAYER==0){
    for(int i=tid;i<TT+HALO;i+=256){
      int t=t0-HALO+i;
      if(t>=0){
        float v[DM]; float ss=0.f;
        #pragma unroll
        for(int d=0;d<DM;d++){ v[d]=x[(b*LEN+t)*DM+d]; ss=fmaf(v[d],v[d],ss); }
        float r=rsqrtf(ss*(1.f/DM)+EPSV);
        #pragma unroll
        for(int d=0;d<DM;d++) sm[S_U+i*DM+d]=v[d]*r*nw[d];
      } else {
        #pragma unroll
        for(int d=0;d<DM;d++) sm[S_U+i*DM+d]=0.f;
      }
    }
    __syncthreads();
  } else {
    // Stage A: gather gated y (coalesced: g_y1 and g_z0 both (b,e,t))
    for(int idx=tid; idx<EDx*(TT+HALO); idx+=256){
      int e=idx/(TT+HALO), i=idx-e*(TT+HALO); int t=t0-HALO+i;
      float g=0.f;
      if(t>=0){
        float yv=g_y1[(b*EDx+e)*LEN+t];
        float zv=g_z0[(b*EDx+e)*LEN+t];
        g=yv*siluf(zv);
      }
      sm[S_SP+e*(TT+HALO)+i]=g;
    }
    __syncthreads();
    // Stage B phase 1: parallel over (i,d): raw h = x + g @ out_proj
    for(int idx=tid; idx<(TT+HALO)*DM; idx+=256){
      int i=idx/DM, d=idx-i*DM; int t=t0-HALO+i;
      float a=0.f;
      if(t>=0){
        a=x[(b*LEN+t)*DM+d];
        #pragma unroll 12
        for(int e=0;e<EDx;e++) a=fmaf(sm[S_SP+e*(TT+HALO)+i], sm[S_OW+e*DM+d], a);
      }
      sm[S_U+idx]=a;
    }
    __syncthreads();
    // Stage B phase 2: rmsnorm in place
    for(int i=tid;i<TT+HALO;i+=256){
      float ss=0.f;
      #pragma unroll
      for(int d=0;d<DM;d++){ float v=sm[S_U+i*DM+d]; ss=fmaf(v,v,ss); }
      float r=rsqrtf(ss*(1.f/DM)+EPSV);
      #pragma unroll
      for(int d=0;d<DM;d++) sm[S_U+i*DM+d]*= r*nw[d];
    }
    __syncthreads();
  }
  // pre-conv xs = u @ Win[:, :48]   (SP[i*48+c])
  for(int idx=tid; idx<(TT+HALO)*EDx; idx+=256){
    int i=idx/EDx, c=idx-i*EDx;
    const float* u=&sm[S_U+i*DM];
    float a=0.f;
    #pragma unroll
    for(int d=0;d<DM;d++) a=fmaf(u[d], __ldg(&Win[d*96+c]), a);
    sm[S_SP+idx]=a;
  }
  // z = u @ Win[:, 48:]
  if (LAYER==0){
    for(int idx=tid; idx<TT*EDx; idx+=256){
      int e=idx>>6, j=idx&63;
      const float* u=&sm[S_U+(j+HALO)*DM];
      float a=0.f;
      #pragma unroll
      for(int d=0;d<DM;d++) a=fmaf(u[d], __ldg(&Win[d*96+48+e]), a);
      g_z0[(b*EDx+e)*LEN + t0 + j]=a;
    }
  } else {
    if (tile==15 && tid<EDx){
      const float* u=&sm[S_U+78*DM];
      float a=0.f;
      #pragma unroll
      for(int d=0;d<DM;d++) a=fmaf(u[d], __ldg(&Win[d*96+48+tid]), a);
      g_lastz[b*EDx+tid]=a;
    }
  }
  __syncthreads();
  // causal depthwise conv + bias + silu -> XC[c*65+j]
  for(int idx=tid; idx<TT*EDx; idx+=256){
    int j=idx/EDx, c=idx-j*EDx;
    float a=convb[c];
    #pragma unroll
    for(int k=0;k<16;k++) a=fmaf(sm[S_CW+c*16+k], sm[S_SP+(j+k)*EDx+c], a);
    sm[S_XC+c*65+j]=siluf(a);
  }
  __syncthreads();
  // load x_proj weights into SP (pre-xs dead)
  for(int i=tid;i<EDx*65;i+=256) sm[S_SP+i]=Wx[i];
  __syncthreads();
  // x_proj: thread = (j, quarter)
  {
    int j=tid>>2, q=tid&3;
    float xr[EDx];
    #pragma unroll
    for(int c=0;c<EDx;c++) xr[c]=sm[S_XC+c*65+j];
    int t=t0+j;
    int m0 = q? (16*q+1):0;
    int m1 = 16*q+17;
    for(int m=m0;m<m1;m++){
      float a=0.f;
      #pragma unroll
      for(int c=0;c<EDx;c++) a=fmaf(xr[c], sm[S_SP+c*65+m], a);
      if(m==0) sm[S_DLT+j]=a;
      else if(m<=32){
        sm[S_SB+j*33+(m-1)]=a;
        if(LAYER==0) ((float*)g_BC0)[((size_t)b*LEN+t)*(2*NS) + (m-1)*2]=a;
      } else {
        if(LAYER==0) ((float*)g_BC0)[((size_t)b*LEN+t)*(2*NS) + (m-33)*2+1]=a;
        else if(tile==15 && j==63) g_lastC[b*NS+(m-33)]=a;
      }
    }
  }
  __syncthreads();
  // delta = softplus(...); store into SP[e*64+j]; per-halfchunk delta sums
  for(int idx=tid; idx<EDx*TT; idx+=256){
    int e=idx>>6, j=idx&63;
    float delta = softplusf(fmaf(sm[S_DLT+j], dtw[e], dtb[e]));
    float s = warpsum(delta);
    if((j&31)==0) sm[S_DSUM+e*2+(j>>5)]=s;
    sm[S_SP+e*64+j]=delta;
    if(LAYER==0)
      g_P0[(b*EDx+e)*LEN + t0 + j] = make_float2(delta, sm[S_XC+e*65+j]);
  }
  if (LAYER==1 && tile==15 && tid<EDx) g_lastxs[b*EDx+tid]=sm[S_XC+tid*65+63];
  __syncthreads();
  // segA: warp w owns e = w, w+8, ..., w+40. Both halfchunks -> compose tile.
  {
    int w=tid>>5, n=tid&31;
    for(int eo=0; eo<6; eo++){
      int e = w + eo*8;
      float acoef = -__expf(alog[e*NS+n])*L2E;
      float H0=0.f;
      #pragma unroll
      for(int s=0;s<CL;s++){
        float dl=sm[S_SP+e*64+s];
        float xs=sm[S_XC+e*65+s];
        float Bv=sm[S_SB+s*33+n];
        H0=fmaf(ex2f(dl*acoef),H0,(dl*xs)*Bv);
      }
      float A0=ex2f(acoef*sm[S_DSUM+e*2+0]);
      float H1=0.f;
      #pragma unroll
      for(int s=CL;s<TT;s++){
        float dl=sm[S_SP+e*64+s];
        float xs=sm[S_XC+e*65+s];
        float Bv=sm[S_SB+s*33+n];
        H1=fmaf(ex2f(dl*acoef),H1,(dl*xs)*Bv);
      }
      float A1=ex2f(acoef*sm[S_DSUM+e*2+1]);
      size_t o = ((size_t)(b*EDx+e)*NT + tile)*NS + n;
      float2 tl = make_float2(A0*A1, fmaf(A1,H0,H1));
      if(LAYER==0){ g_half0[o]=make_float2(A0,H0); g_tile0[o]=tl; }
      else        { g_tile1[o]=tl; }
    }
  }
}

// Layer-1 replay: block = (b, chunk, e-sixth); BC + P staged in smem.
__global__ void __launch_bounds__(512) k_segC(const float* __restrict__ alog,
                                              const float* __restrict__ Dw)
{
  __shared__ float2 sBC[CL*NS];     // 8KB  [j*32+n]
  __shared__ float2 sP [16*CL];     // 4KB  [el*32+j]
  int blk=blockIdx.x;
  int eg = blk % 3;
  int c  = (blk/3) % NCH;
  int b  = blk/(3*NCH);
  int tid= threadIdx.x;
  int w=tid>>5, n=tid&31;
  int e = eg*16 + w;

  for(int idx=tid; idx<CL*NS; idx+=512)
    sBC[idx]=g_BC0[((size_t)b*LEN + c*CL + (idx>>5))*NS + (idx&31)];
  for(int idx=tid; idx<16*CL; idx+=512)
    sP[idx]=g_P0[(b*EDx + eg*16 + (idx>>5))*LEN + c*CL + (idx&31)];
  __syncthreads();

  float acoef = -__expf(alog[e*NS+n])*L2E;
  // hierarchical lookback: full tiles, then one halfchunk if odd
  int T = c>>1;
  const float2* TS=&g_tile0[((size_t)(b*EDx+e)*NT)*NS + n];
  float h=0.f;
  #pragma unroll 4
  for(int tt=0;tt<T;tt++){ float2 s=TS[tt*NS]; h=fmaf(s.x,h,s.y); }
  if(c&1){ float2 s=g_half0[((size_t)(b*EDx+e)*NT+T)*NS+n]; h=fmaf(s.x,h,s.y); }

  const float2* P = &sP[w*CL];
  float acc0,acc1,acc2,acc3,acc4,res=0.f;
  #pragma unroll
  for(int j=0;j<CL;j++){
    float2 p  = P[j];
    float2 bc = sBC[j*NS+n];
    float a = ex2f(p.x*acoef);
    h = fmaf(a, h, (p.x*p.y)*bc.x);
    float cur = h*bc.y;
    if (j&1){ cur=mergef(acc0,cur,1);
      if(j&2){ cur=mergef(acc1,cur,2);
        if(j&4){ cur=mergef(acc2,cur,4);
          if(j&8){ cur=mergef(acc3,cur,8);
            if(j&16){ res=mergef(acc4,cur,16); }
            else acc4=cur; }
          else acc3=cur; }
        else acc2=cur; }
      else acc1=cur; }
    else acc0=cur;
  }
  g_y1[(b*EDx+e)*LEN + c*CL + n] = fmaf(Dw[e], P[n].y, res);
}

// Layer-2 final combine (16 tile summaries) + feature + fused head.
__global__ void __launch_bounds__(128) k_comb2final(
   const float* __restrict__ Dw,
   const float* __restrict__ fcw, const float* __restrict__ fcb,
   const float* __restrict__ clsw, const float* __restrict__ clsb,
   const float* __restrict__ regw, const float* __restrict__ regb,
   float* __restrict__ out)
{
  __shared__ float feat[BN*EDx];
  __shared__ int isLast;
  int b = blockIdx.x/12;
  int e = (blockIdx.x%12)*4 + threadIdx.y;
  int n = threadIdx.x;
  int tid = threadIdx.y*32+n;
  const float2* S = &g_tile1[((size_t)(b*EDx+e)*NT)*NS + n];
  float h=0.f;
  #pragma unroll
  for(int tt=0;tt<NT;tt++){ float2 s=S[tt*NS]; h=fmaf(s.x,h,s.y); }
  float sv = warpsum(h * g_lastC[b*NS+n]);
  if(n==0){
    float y = fmaf(Dw[e], g_lastxs[b*EDx+e], sv);
    g_fi[b*EDx+e] = y * siluf(g_lastz[b*EDx+e]);
  }
  __threadfence();
  __syncthreads();
  if(tid==0){ unsigned old=atomicAdd(&g_ctr,1u); isLast = (old==(unsigned)(gridDim.x-1)); }
  __syncthreads();
  if(!isLast) return;
  if(tid==0) g_ctr=0;
  __threadfence();
  for(int idx=tid; idx<BN*EDx; idx+=128){
    int bb=idx/EDx, j=idx-bb*EDx;
    float a=fcb[j];
    #pragma unroll 12
    for(int ee=0;ee<EDx;ee++) a=fmaf(g_fi[bb*EDx+ee], fcw[ee*EDx+j], a);
    feat[idx]=fmaxf(a,0.f);
  }
  __syncthreads();
  if(tid<BN*4){
    int bb=tid>>2,k=tid&3;
    float a=clsb[k];
    #pragma unroll 12
    for(int j=0;j<EDx;j++) a=fmaf(feat[bb*EDx+j], clsw[j*4+k], a);
    out[bb*4+k]=a;
  } else if(tid<BN*4+BN){
    int bb=tid-BN*4;
    float a=regb[0];
    #pragma unroll 12
    for(int j=0;j<EDx;j++) a=fmaf(feat[bb*EDx+j], regw[j], a);
    out[BN*4+bb]=a;
  }
}

extern "C" void kernel_launch(void* const* d_in, const int* in_sizes, int n_in,
                              void* d_out, int out_size)
{
  const float* x    =(const float*)d_in[0];
  const float* ipw  =(const float*)d_in[1];   // (2,6,96)
  const float* cw   =(const float*)d_in[2];   // (2,48,16)
  const float* cb   =(const float*)d_in[3];   // (2,48)
  const float* xpw  =(const float*)d_in[4];   // (2,48,65)
  const float* dtw  =(const float*)d_in[5];   // (2,1,48)
  const float* dtb  =(const float*)d_in[6];   // (2,48)
  const float* alog =(const float*)d_in[7];   // (2,48,32)
  const float* Dw   =(const float*)d_in[8];   // (2,48)
  const float* nw   =(const float*)d_in[9];   // (2,6)
  const float* ow   =(const float*)d_in[10];  // (1,48,6)
  const float* fcw  =(const float*)d_in[11];
  const float* fcb  =(const float*)d_in[12];
  const float* clsw =(const float*)d_in[13];
  const float* clsb =(const float*)d_in[14];
  const float* regw =(const float*)d_in[15];
  const float* regb =(const float*)d_in[16];
  float* out = (float*)d_out;

  k_preA<0><<<BN*NT, 256>>>(x, ipw, cw, cb, xpw, dtw, dtb, alog, nw, ow);
  k_segC   <<<BN*NCH*3, 512>>>(alog, Dw);
  k_preA<1><<<BN*NT, 256>>>(x, ipw+6*96, cw+768, cb+48, xpw+3120,
                            dtw+48, dtb+48, alog+1536, nw+DM, ow);
  k_comb2final<<<BN*12, dim3(32,4)>>>(Dw+48, fcw, fcb, clsw, clsb, regw, regb, out);
}